// round 1
// baseline (speedup 1.0000x reference)
#include <cuda_runtime.h>
#include <cuda_bf16.h>
#include <cstdint>

#define N_NODES   100000
#define N_EDGES   1600000
#define IN_FEATS  64
#define OUT_FEATS 64
#define DIM       3
#define N_KERNELS 4
#define KH        (N_KERNELS * OUT_FEATS)   // 256

// Scratch for node projections h[N, K*OUT] (allocation-free rule: __device__ global)
__device__ float g_h[(size_t)N_NODES * KH];

// ---------------------------------------------------------------------------
// Kernel 1: out = feat + bias  (vectorized float4)
// ---------------------------------------------------------------------------
__global__ void init_out_kernel(const float* __restrict__ feat,
                                const float* __restrict__ bias,
                                float* __restrict__ out) {
    int i = blockIdx.x * blockDim.x + threadIdx.x;           // float4 index
    const int total4 = N_NODES * OUT_FEATS / 4;              // 1.6M
    if (i >= total4) return;
    float4 f = reinterpret_cast<const float4*>(feat)[i];
    float4 b = reinterpret_cast<const float4*>(bias)[i & 15]; // 64/4 = 16 float4 per row
    f.x += b.x; f.y += b.y; f.z += b.z; f.w += b.w;
    reinterpret_cast<float4*>(out)[i] = f;
}

// ---------------------------------------------------------------------------
// Kernel 2: h[v, o] = sum_j feat[v,j] * W_fc[o, j]   (o in [0,256), j in [0,64))
// Block: 256 threads (one output channel each), TILE nodes per block.
// Each thread keeps its W row (64 floats) in registers; feat tile in shared.
// ---------------------------------------------------------------------------
#define PROJ_TILE 32

__global__ __launch_bounds__(256) void proj_kernel(const float* __restrict__ feat,
                                                   const float* __restrict__ W_fc) {
    __shared__ float sf[PROJ_TILE][IN_FEATS];

    const int o = threadIdx.x;                 // 0..255 output channel
    const int node0 = blockIdx.x * PROJ_TILE;

    // Load W row into registers (16 x float4)
    float w[IN_FEATS];
    const float4* wp = reinterpret_cast<const float4*>(W_fc + (size_t)o * IN_FEATS);
#pragma unroll
    for (int q = 0; q < IN_FEATS / 4; q++) {
        float4 v = wp[q];
        w[4*q+0] = v.x; w[4*q+1] = v.y; w[4*q+2] = v.z; w[4*q+3] = v.w;
    }

    // Cooperative load of feat tile: 32*64 floats = 512 float4 by 256 threads
    const float4* fp = reinterpret_cast<const float4*>(feat + (size_t)node0 * IN_FEATS);
#pragma unroll
    for (int q = 0; q < 2; q++) {
        int idx = threadIdx.x + q * 256;       // float4 index within tile
        float4 v = fp[idx];
        int n = idx >> 4;                       // 16 float4 per node row
        int c = (idx & 15) * 4;
        sf[n][c+0] = v.x; sf[n][c+1] = v.y; sf[n][c+2] = v.z; sf[n][c+3] = v.w;
    }
    __syncthreads();

#pragma unroll 4
    for (int n = 0; n < PROJ_TILE; n++) {
        float acc = 0.f;
#pragma unroll
        for (int j = 0; j < IN_FEATS; j++)
            acc = fmaf(w[j], sf[n][j], acc);
        g_h[(size_t)(node0 + n) * KH + o] = acc;
    }
}

// ---------------------------------------------------------------------------
// Kernel 3: edge scatter.
// 16 threads per edge; lane handles 4 consecutive output channels.
// Gaussian weight g[k] computed once per (edge,k) by lane with kid = lane&3,
// broadcast via shfl within the 16-lane group.
// Scatter via red.global.add.v4.f32 (sm_90+ vector reduction).
// ---------------------------------------------------------------------------
__global__ __launch_bounds__(256) void edge_kernel(const float* __restrict__ pseudo,
                                                   const int*   __restrict__ src,
                                                   const int*   __restrict__ dst,
                                                   const float* __restrict__ mu,
                                                   const float* __restrict__ inv_sigma,
                                                   float* __restrict__ out) {
    const int gid = blockIdx.x * blockDim.x + threadIdx.x;
    const int e   = gid >> 4;                  // edge index
    if (e >= N_EDGES) return;

    const int lane = threadIdx.x & 31;
    const int sub  = gid & 15;                 // 0..15 within edge group
    const int kid  = sub & 3;                  // which Gaussian kernel this lane evaluates

    // --- Gaussian weight for kernel `kid` ---
    float px = __ldg(pseudo + 3*e + 0);
    float py = __ldg(pseudo + 3*e + 1);
    float pz = __ldg(pseudo + 3*e + 2);

    float d0 = px - __ldg(mu + kid*3 + 0);
    float d1 = py - __ldg(mu + kid*3 + 1);
    float d2 = pz - __ldg(mu + kid*3 + 2);
    float s0 = __ldg(inv_sigma + kid*3 + 0);
    float s1 = __ldg(inv_sigma + kid*3 + 1);
    float s2 = __ldg(inv_sigma + kid*3 + 2);

    float acc = d0*d0*s0*s0 + d1*d1*s1*s1 + d2*d2*s2*s2;
    float gv  = __expf(-0.5f * acc);

    // Broadcast g[0..3] within the 16-lane group (group base = lane & 16)
    const unsigned FULL = 0xffffffffu;
    const int base = lane & 16;
    float g0 = __shfl_sync(FULL, gv, base + 0);
    float g1 = __shfl_sync(FULL, gv, base + 1);
    float g2 = __shfl_sync(FULL, gv, base + 2);
    float g3 = __shfl_sync(FULL, gv, base + 3);

    const int s = __ldg(src + e);
    const int d = __ldg(dst + e);

    // Gather h[src, k*64 + sub*4 .. +3] for k = 0..3 (float4 each)
    const float4* hp = reinterpret_cast<const float4*>(g_h + (size_t)s * KH);
    float4 a0 = __ldg(hp + 0*16 + sub);
    float4 a1 = __ldg(hp + 1*16 + sub);
    float4 a2 = __ldg(hp + 2*16 + sub);
    float4 a3 = __ldg(hp + 3*16 + sub);

    float4 m;
    m.x = g0*a0.x + g1*a1.x + g2*a2.x + g3*a3.x;
    m.y = g0*a0.y + g1*a1.y + g2*a2.y + g3*a3.y;
    m.z = g0*a0.z + g1*a1.z + g2*a2.z + g3*a3.z;
    m.w = g0*a0.w + g1*a1.w + g2*a2.w + g3*a3.w;

    float* op = out + (size_t)d * OUT_FEATS + sub * 4;
    asm volatile("red.global.add.v4.f32 [%0], {%1, %2, %3, %4};"
                 :: "l"(op), "f"(m.x), "f"(m.y), "f"(m.z), "f"(m.w)
                 : "memory");
}

// ---------------------------------------------------------------------------
// Launch
// ---------------------------------------------------------------------------
extern "C" void kernel_launch(void* const* d_in, const int* in_sizes, int n_in,
                              void* d_out, int out_size) {
    const float* feat      = (const float*)d_in[0];   // [N, 64]
    const float* pseudo    = (const float*)d_in[1];   // [E, 3]
    const int*   src       = (const int*)  d_in[2];   // [E]
    const int*   dst       = (const int*)  d_in[3];   // [E]
    const float* W_fc      = (const float*)d_in[4];   // [256, 64]
    const float* mu        = (const float*)d_in[5];   // [4, 3]
    const float* inv_sigma = (const float*)d_in[6];   // [4, 3]
    const float* bias      = (const float*)d_in[7];   // [64]
    float* out = (float*)d_out;                       // [N, 64]

    // 1) out = feat + bias
    {
        int total4 = N_NODES * OUT_FEATS / 4;
        init_out_kernel<<<(total4 + 255) / 256, 256>>>(feat, bias, out);
    }
    // 2) h = feat @ W_fc^T   (independent of 1; stream order is fine)
    {
        int blocks = (N_NODES + PROJ_TILE - 1) / PROJ_TILE;   // 3125
        proj_kernel<<<blocks, 256>>>(feat, W_fc);
    }
    // 3) edge scatter with atomics
    {
        long long threads = (long long)N_EDGES * 16;
        int blocks = (int)((threads + 255) / 256);            // 100000
        edge_kernel<<<blocks, 256>>>(pseudo, src, dst, mu, inv_sigma, out);
    }
}

// round 2
// speedup vs baseline: 1.1181x; 1.1181x over previous
#include <cuda_runtime.h>
#include <cuda_fp16.h>
#include <cuda_bf16.h>
#include <cstdint>

#define N_NODES   100000
#define N_EDGES   1600000
#define IN_FEATS  64
#define OUT_FEATS 64
#define DIM       3
#define N_KERNELS 4
#define KH        (N_KERNELS * OUT_FEATS)   // 256

// Scratch for node projections h[N, K*OUT] in fp16 (allocation-free rule)
__device__ __half g_h[(size_t)N_NODES * KH];

// ---------------------------------------------------------------------------
// Kernel 1: out = feat + bias  (vectorized float4)
// ---------------------------------------------------------------------------
__global__ void init_out_kernel(const float* __restrict__ feat,
                                const float* __restrict__ bias,
                                float* __restrict__ out) {
    int i = blockIdx.x * blockDim.x + threadIdx.x;           // float4 index
    const int total4 = N_NODES * OUT_FEATS / 4;              // 1.6M
    if (i >= total4) return;
    float4 f = reinterpret_cast<const float4*>(feat)[i];
    float4 b = reinterpret_cast<const float4*>(bias)[i & 15]; // 16 float4 per row
    f.x += b.x; f.y += b.y; f.z += b.z; f.w += b.w;
    reinterpret_cast<float4*>(out)[i] = f;
}

// ---------------------------------------------------------------------------
// Kernel 2: h[v, o] = sum_j feat[v,j] * W_fc[o, j]  -> fp16
// Block: 256 threads (one output channel each), PROJ_TILE nodes per block.
// ---------------------------------------------------------------------------
#define PROJ_TILE 32

__global__ __launch_bounds__(256) void proj_kernel(const float* __restrict__ feat,
                                                   const float* __restrict__ W_fc) {
    __shared__ float sf[PROJ_TILE][IN_FEATS];

    const int o = threadIdx.x;                 // 0..255 output channel
    const int node0 = blockIdx.x * PROJ_TILE;

    // W row into registers (16 x float4)
    float w[IN_FEATS];
    const float4* wp = reinterpret_cast<const float4*>(W_fc + (size_t)o * IN_FEATS);
#pragma unroll
    for (int q = 0; q < IN_FEATS / 4; q++) {
        float4 v = wp[q];
        w[4*q+0] = v.x; w[4*q+1] = v.y; w[4*q+2] = v.z; w[4*q+3] = v.w;
    }

    // Cooperative feat tile load: 32*64 floats = 512 float4 by 256 threads
    const float4* fp = reinterpret_cast<const float4*>(feat + (size_t)node0 * IN_FEATS);
#pragma unroll
    for (int q = 0; q < 2; q++) {
        int idx = threadIdx.x + q * 256;
        float4 v = fp[idx];
        int n = idx >> 4;                       // 16 float4 per node row
        int c = (idx & 15) * 4;
        sf[n][c+0] = v.x; sf[n][c+1] = v.y; sf[n][c+2] = v.z; sf[n][c+3] = v.w;
    }
    __syncthreads();

#pragma unroll 4
    for (int n = 0; n < PROJ_TILE; n++) {
        float acc = 0.f;
#pragma unroll
        for (int j = 0; j < IN_FEATS; j++)
            acc = fmaf(w[j], sf[n][j], acc);
        g_h[(size_t)(node0 + n) * KH + o] = __float2half_rn(acc);
    }
}

// ---------------------------------------------------------------------------
// Kernel 3: edge scatter.
// 8 threads per edge; thread handles 8 consecutive output channels.
// Per kernel k: one 16-B load (8 halves) -> 128B coalesced per 8-lane group.
// Gaussian weights: lanes with kid=sub&3 compute one exp each; shfl broadcast.
// Scatter via 2x red.global.add.v4.f32.
// ---------------------------------------------------------------------------
__global__ __launch_bounds__(256) void edge_kernel(const float* __restrict__ pseudo,
                                                   const int*   __restrict__ src,
                                                   const int*   __restrict__ dst,
                                                   const float* __restrict__ mu,
                                                   const float* __restrict__ inv_sigma,
                                                   float* __restrict__ out) {
    const int gid = blockIdx.x * blockDim.x + threadIdx.x;
    const int e   = gid >> 3;                  // edge index
    if (e >= N_EDGES) return;

    const int lane = threadIdx.x & 31;
    const int sub  = gid & 7;                  // 0..7 within edge group
    const int kid  = sub & 3;                  // Gaussian kernel this lane evaluates

    // --- Gaussian weight for kernel `kid` ---
    float px = __ldg(pseudo + 3*e + 0);
    float py = __ldg(pseudo + 3*e + 1);
    float pz = __ldg(pseudo + 3*e + 2);

    float d0 = px - __ldg(mu + kid*3 + 0);
    float d1 = py - __ldg(mu + kid*3 + 1);
    float d2 = pz - __ldg(mu + kid*3 + 2);
    float s0 = __ldg(inv_sigma + kid*3 + 0);
    float s1 = __ldg(inv_sigma + kid*3 + 1);
    float s2 = __ldg(inv_sigma + kid*3 + 2);

    float acc = d0*d0*s0*s0 + d1*d1*s1*s1 + d2*d2*s2*s2;
    float gv  = __expf(-0.5f * acc);

    // Broadcast g[0..3] within the 8-lane group (group base = lane & 24)
    const unsigned FULL = 0xffffffffu;
    const int base = lane & 24;
    float g0 = __shfl_sync(FULL, gv, base + 0);
    float g1 = __shfl_sync(FULL, gv, base + 1);
    float g2 = __shfl_sync(FULL, gv, base + 2);
    float g3 = __shfl_sync(FULL, gv, base + 3);

    const int s = __ldg(src + e);
    const int d = __ldg(dst + e);

    // Gather h[src, k*64 + sub*8 .. +7] (8 halves = 16 B) for k = 0..3
    const float4* hp = reinterpret_cast<const float4*>(g_h + (size_t)s * KH);
    float4 r0 = __ldg(hp + 0*8 + sub);
    float4 r1 = __ldg(hp + 1*8 + sub);
    float4 r2 = __ldg(hp + 2*8 + sub);
    float4 r3 = __ldg(hp + 3*8 + sub);

    const __half2* h0 = reinterpret_cast<const __half2*>(&r0);
    const __half2* h1 = reinterpret_cast<const __half2*>(&r1);
    const __half2* h2 = reinterpret_cast<const __half2*>(&r2);
    const __half2* h3 = reinterpret_cast<const __half2*>(&r3);

    float m[8];
#pragma unroll
    for (int q = 0; q < 4; q++) {
        float2 a = __half22float2(h0[q]);
        float2 b = __half22float2(h1[q]);
        float2 c = __half22float2(h2[q]);
        float2 dd = __half22float2(h3[q]);
        m[2*q+0] = g0*a.x + g1*b.x + g2*c.x + g3*dd.x;
        m[2*q+1] = g0*a.y + g1*b.y + g2*c.y + g3*dd.y;
    }

    float* op = out + (size_t)d * OUT_FEATS + sub * 8;
    asm volatile("red.global.add.v4.f32 [%0], {%1, %2, %3, %4};"
                 :: "l"(op), "f"(m[0]), "f"(m[1]), "f"(m[2]), "f"(m[3])
                 : "memory");
    asm volatile("red.global.add.v4.f32 [%0], {%1, %2, %3, %4};"
                 :: "l"(op + 4), "f"(m[4]), "f"(m[5]), "f"(m[6]), "f"(m[7])
                 : "memory");
}

// ---------------------------------------------------------------------------
// Launch
// ---------------------------------------------------------------------------
extern "C" void kernel_launch(void* const* d_in, const int* in_sizes, int n_in,
                              void* d_out, int out_size) {
    const float* feat      = (const float*)d_in[0];   // [N, 64]
    const float* pseudo    = (const float*)d_in[1];   // [E, 3]
    const int*   src       = (const int*)  d_in[2];   // [E]
    const int*   dst       = (const int*)  d_in[3];   // [E]
    const float* W_fc      = (const float*)d_in[4];   // [256, 64]
    const float* mu        = (const float*)d_in[5];   // [4, 3]
    const float* inv_sigma = (const float*)d_in[6];   // [4, 3]
    const float* bias      = (const float*)d_in[7];   // [64]
    float* out = (float*)d_out;                       // [N, 64]

    // 1) out = feat + bias
    {
        int total4 = N_NODES * OUT_FEATS / 4;
        init_out_kernel<<<(total4 + 255) / 256, 256>>>(feat, bias, out);
    }
    // 2) h = feat @ W_fc^T  (fp16 output)
    {
        int blocks = (N_NODES + PROJ_TILE - 1) / PROJ_TILE;   // 3125
        proj_kernel<<<blocks, 256>>>(feat, W_fc);
    }
    // 3) edge scatter with vector atomics
    {
        long long threads = (long long)N_EDGES * 8;
        int blocks = (int)((threads + 255) / 256);            // 50000
        edge_kernel<<<blocks, 256>>>(pseudo, src, dst, mu, inv_sigma, out);
    }
}